// round 14
// baseline (speedup 1.0000x reference)
#include <cuda_runtime.h>
#include <cuda_bf16.h>
#include <cuda_fp16.h>
#include <cstdint>

#define SS 4096
#define KK 64
#define NN 4096
#define GG 512
#define PP (SS*KK)

// ---------------- scratch (no allocation allowed) ----------------
__device__ int d_flag64;
__device__ __align__(16) int d_mi[PP];
__device__ __align__(16) int d_ai[PP];
__device__ __align__(16) int d_phi[PP];
__device__ __align__(16) int d_cnt[SS];
__device__ __align__(16) __half d_gh[NN*GG];             // g_i in fp16
__device__ __align__(16) unsigned char d_wct[81920];     // W1c^T * 64, e4m3, mma-fragment order
__device__ __align__(16) __nv_bfloat16 d_Ub[NN*160];     // g @ W1a (bf16), pad cols zero
__device__ __align__(16) __nv_bfloat16 d_Vb[NN*160];     // g @ W1b (bf16)
__device__ __align__(16) __nv_bfloat16 d_Tb[192*160];    // phi-combo @ W1d + b1 (bf16)

// ---------------- helpers ----------------
__device__ __forceinline__ uint32_t smem_u32(const void* p) {
    uint32_t a;
    asm("{ .reg .u64 t; cvta.to.shared.u64 t, %1; cvt.u32.u64 %0, t; }" : "=r"(a) : "l"(p));
    return a;
}
// pack two f32 -> two e4m3 bytes (lo = first arg)
__device__ __forceinline__ unsigned short f2e(float lo, float hi) {
    unsigned short r;
    asm("cvt.rn.satfinite.e4m3x2.f32 %0, %1, %2;" : "=h"(r) : "f"(hi), "f"(lo));
    return r;
}
// f16x2 -> e4m3x2 (elementwise, byte0 = low half)
__device__ __forceinline__ unsigned short h2e(unsigned h2) {
    unsigned short r;
    asm("cvt.rn.satfinite.e4m3x2.f16x2 %0, %1;" : "=h"(r) : "r"(h2));
    return r;
}
__device__ __forceinline__ unsigned hm2(unsigned x, unsigned y) {
    __half2 a = *reinterpret_cast<__half2*>(&x);
    __half2 b = *reinterpret_cast<__half2*>(&y);
    __half2 c = __hmul2(a, b);
    return *reinterpret_cast<unsigned*>(&c);
}
__device__ __forceinline__ float2 b2f(unsigned u) {
    __nv_bfloat162 h = *reinterpret_cast<__nv_bfloat162*>(&u);
    return __bfloat1622float2(h);
}

// ---------------- precompute kernels ----------------
__global__ void k_detect(const unsigned* __restrict__ m) {
    if (threadIdx.x == 0) {
        unsigned acc = 0;
        for (int t = 0; t < 64; t++) acc |= m[2*t + 1];
        d_flag64 = (acc == 0) ? 1 : 0;
    }
}

__global__ void k_index(const void* __restrict__ mi, const void* __restrict__ ai,
                        const void* __restrict__ di, const void* __restrict__ ge,
                        const void* __restrict__ sp, const void* __restrict__ ac) {
    int p = blockIdx.x * blockDim.x + threadIdx.x;
    int f = d_flag64;
    if (p < PP) {
        int a, b; long long d, gg, ss;
        if (f) {
            a = (int)((const long long*)mi)[p];
            b = (int)((const long long*)ai)[p];
            d  = ((const long long*)di)[p];
            gg = ((const long long*)ge)[p];
            ss = ((const long long*)sp)[p];
        } else {
            a = ((const int*)mi)[p];
            b = ((const int*)ai)[p];
            d  = ((const int*)di)[p];
            gg = ((const int*)ge)[p];
            ss = ((const int*)sp)[p];
        }
        int bk = (d>=1)+(d>=2)+(d>=3)+(d>=4)+(d>=8)+(d>=16)+(d>=32)+(d>=64);
        d_mi[p] = a;
        d_ai[p] = b;
        d_phi[p] = bk*21 + (int)gg*3 + (int)ss;
    }
    if (p < SS) {
        d_cnt[p] = f ? (int)((const long long*)ac)[p] : ((const int*)ac)[p];
    }
}

__global__ void k_gh(const float* __restrict__ g) {
    int i = blockIdx.x * 256 + threadIdx.x;
    if (i < NN*GG) d_gh[i] = __float2half(g[i]);
}

// W1c^T * 64 packed as e4m3 in m16n8k32 B-fragment order:
// uint2 index = (kc*20 + nf)*32 + lane; n = nf*8 + lane/4, t4 = lane%4
//   w.x bytes h=0..3 : k = kc*32 + 4*t4 + h      (b0)
//   w.y bytes h=0..3 : k = kc*32 + 16 + 4*t4 + h (b1)
__global__ void k_wct(const float* __restrict__ W1) {
    int gid = blockIdx.x * 256 + threadIdx.x;   // uint2 index, 0..10239
    if (gid < 10240) {
        int kc = gid / 640;
        int r  = gid - kc*640;
        int nf = r >> 5;
        int lane = r & 31;
        int n  = nf*8 + (lane >> 2);
        int t4 = lane & 3;
        float v[8];
        #pragma unroll
        for (int h = 0; h < 4; h++) {
            int k0 = kc*32 + 4*t4 + h;
            int k1 = k0 + 16;
            v[h]     = (n < 150) ? W1[(size_t)(1024 + k0)*150 + n] * 64.f : 0.f;
            v[4 + h] = (n < 150) ? W1[(size_t)(1024 + k1)*150 + n] * 64.f : 0.f;
        }
        uint2 w;
        w.x = (unsigned)f2e(v[0], v[1]) | ((unsigned)f2e(v[2], v[3]) << 16);
        w.y = (unsigned)f2e(v[4], v[5]) | ((unsigned)f2e(v[6], v[7]) << 16);
        ((uint2*)d_wct)[gid] = w;
    }
}

__global__ void k_T(const float* __restrict__ de, const float* __restrict__ ge,
                    const float* __restrict__ se, const float* __restrict__ W1,
                    const float* __restrict__ b1) {
    int gid = blockIdx.x * blockDim.x + threadIdx.x;
    if (gid >= 192*160) return;
    int c = gid / 160, m = gid % 160;
    int d = c / 21, rr = c % 21, gg = rr / 3, sp = rr % 3;
    float val = 0.f;
    if (m < 150 && d < 9) {
        val = b1[m];
        #pragma unroll 4
        for (int q = 0; q < 20; q++) {
            val += de[d*20 + q]  * W1[(size_t)(1536 + q)*150 + m];
            val += ge[gg*20 + q] * W1[(size_t)(1556 + q)*150 + m];
            val += se[sp*20 + q] * W1[(size_t)(1576 + q)*150 + m];
        }
    }
    d_Tb[gid] = __float2bfloat16(val);
}

__global__ __launch_bounds__(160) void k_uv(const float* __restrict__ g,
                                            const float* __restrict__ W1) {
    __shared__ float gs[8*512];
    int n0 = blockIdx.x * 8;
    for (int idx = threadIdx.x; idx < 8*512; idx += 160)
        gs[idx] = g[(size_t)n0*512 + idx];
    __syncthreads();
    int m = threadIdx.x;
    if (m < 150) {
        float aU[8], aV[8];
        #pragma unroll
        for (int r = 0; r < 8; r++) { aU[r] = 0.f; aV[r] = 0.f; }
        for (int k = 0; k < 512; k++) {
            float wu = W1[(size_t)k*150 + m];
            float wv = W1[(size_t)(512 + k)*150 + m];
            #pragma unroll
            for (int r = 0; r < 8; r++) {
                float gv = gs[r*512 + k];
                aU[r] = fmaf(gv, wu, aU[r]);
                aV[r] = fmaf(gv, wv, aV[r]);
            }
        }
        #pragma unroll
        for (int r = 0; r < 8; r++) {
            d_Ub[(size_t)(n0 + r)*160 + m] = __float2bfloat16(aU[r]);
            d_Vb[(size_t)(n0 + r)*160 + m] = __float2bfloat16(aV[r]);
        }
    } else {
        #pragma unroll
        for (int r = 0; r < 8; r++) {
            d_Ub[(size_t)(n0 + r)*160 + m] = __float2bfloat16(0.f);
            d_Vb[(size_t)(n0 + r)*160 + m] = __float2bfloat16(0.f);
        }
    }
}

// ---------------- main fused kernel (fp8 mma.sync, W in smem) ----------------
// CTA = 128 pairs = 2 spans. 512 threads / 16 warps (8 M-tiles x 2 N-halves).
// smem:
//   Es [128 rows][stride 528B] e4m3, row = 512 data bytes (16 chunks of 32B).
//     528 = 33 x 16B (odd) -> 16B-chunk bank-group = (row + chunk16) mod 8:
//     conflict-free for phase-A STS.128 and ldmatrix.
//   Ws: full W1c fp8 fragment image (identical layout to d_wct), 80 KB.
#define ES_STRIDE 528
#define OFF_A    0
#define OFF_W    67584
#define OFF_MSUM 149504
#define OFF_II   150016
#define OFF_JJ   150528
#define OFF_CC   151040
#define OFF_W2   151552
#define OFF_SC   152192
#define OFF_SR   152704
#define SMEM_MAIN 153728

__global__ __launch_bounds__(512, 1)
void k_main(const float* __restrict__ ms, const float* __restrict__ W2,
            const float* __restrict__ b2, float* __restrict__ out) {
    extern __shared__ char sm[];
    const int t = threadIdx.x;
    const int lane = t & 31, wid = t >> 5;
    const uint32_t sb = smem_u32(sm);
    const int pbase = blockIdx.x * 128;

    float* msum   = (float*)(sm + OFF_MSUM);
    int*   idxI   = (int*)(sm + OFF_II);
    int*   idxJ   = (int*)(sm + OFF_JJ);
    int*   idxC   = (int*)(sm + OFF_CC);
    float* W2s    = (float*)(sm + OFF_W2);
    float* scores = (float*)(sm + OFF_SC);
    float* sred   = (float*)(sm + OFF_SR);

    // ---- Phase A: gather + f16 product -> e4m3 Es tile; stage W into smem ----
    {
        const int pl = t & 127, qq = t >> 7;   // 4 threads per pair, 128 elems each
        const int p = pbase + pl;
        const int i = d_mi[p], j = d_ai[p];
        if (qq == 0) {
            msum[pl] = ms[i] + ms[j];
            idxI[pl] = i; idxJ[pl] = j; idxC[pl] = d_phi[p];
        }
        const uint4* gi4 = (const uint4*)(d_gh + (size_t)i*GG) + qq*16;
        const uint4* gj4 = (const uint4*)(d_gh + (size_t)j*GG) + qq*16;
        char* rowp = sm + OFF_A + pl*ES_STRIDE + qq*128;
        #pragma unroll
        for (int e = 0; e < 8; e++) {
            uint4 a0 = gi4[2*e], a1 = gi4[2*e + 1];
            uint4 c0 = gj4[2*e], c1 = gj4[2*e + 1];
            unsigned p0 = hm2(a0.x, c0.x), p1 = hm2(a0.y, c0.y);
            unsigned p2 = hm2(a0.z, c0.z), p3 = hm2(a0.w, c0.w);
            unsigned p4 = hm2(a1.x, c1.x), p5 = hm2(a1.y, c1.y);
            unsigned p6 = hm2(a1.z, c1.z), p7 = hm2(a1.w, c1.w);
            uint4 r;
            r.x = (unsigned)h2e(p0) | ((unsigned)h2e(p1) << 16);
            r.y = (unsigned)h2e(p2) | ((unsigned)h2e(p3) << 16);
            r.z = (unsigned)h2e(p4) | ((unsigned)h2e(p5) << 16);
            r.w = (unsigned)h2e(p6) | ((unsigned)h2e(p7) << 16);
            *(uint4*)(rowp + e*16) = r;
        }
        // stage W1c fragment image: 5120 uint4, 10 per thread, coalesced
        const uint4* wsrc4 = (const uint4*)d_wct;
        uint4* wdst4 = (uint4*)(sm + OFF_W);
        #pragma unroll
        for (int q = 0; q < 10; q++) wdst4[t + q*512] = wsrc4[t + q*512];
        if (t < 160) W2s[t] = (t < 150) ? __ldg(W2 + t) : 0.f;
    }
    __syncthreads();   // the ONLY barrier before the epilogue

    // ---- K loop: 16 chunks of k32, fp8 mma, B fragments from smem ----
    const int mw = wid >> 1, nw = wid & 1;
    const int g = lane >> 2, t4 = lane & 3;

    // ldmatrix.x4: {m0-7,seg0},{m8-15,seg0},{m0-7,seg1},{m8-15,seg1}, seg = 16B
    const uint32_t arow = sb + OFF_A
        + (uint32_t)(mw*16 + (lane & 7) + (lane & 8)) * ES_STRIDE
        + (uint32_t)((lane >> 4) & 1) * 16;

    const uint2* wsm = (const uint2*)(sm + OFF_W) + nw*320 + lane;

    float acc[10][4];
    #pragma unroll
    for (int q = 0; q < 10; q++)
        #pragma unroll
        for (int e = 0; e < 4; e++) acc[q][e] = 0.f;

    #pragma unroll 4
    for (int kc = 0; kc < 16; kc++) {
        uint32_t a0, a1, a2, a3;
        asm volatile("ldmatrix.sync.aligned.m8n8.x4.shared.b16 {%0,%1,%2,%3}, [%4];"
                     : "=r"(a0), "=r"(a1), "=r"(a2), "=r"(a3)
                     : "r"(arow + (uint32_t)kc*32));
        #pragma unroll
        for (int q = 0; q < 10; q++) {
            uint2 bb = wsm[kc*640 + q*32];
            asm volatile(
                "mma.sync.aligned.m16n8k32.row.col.f32.e4m3.e4m3.f32 "
                "{%0,%1,%2,%3}, {%4,%5,%6,%7}, {%8,%9}, {%0,%1,%2,%3};"
                : "+f"(acc[q][0]), "+f"(acc[q][1]), "+f"(acc[q][2]), "+f"(acc[q][3])
                : "r"(a0), "r"(a1), "r"(a2), "r"(a3), "r"(bb.x), "r"(bb.y));
        }
    }

    // ---- Epilogue: acc/64 + U/V/T gather (bf16 from L2), ReLU, dot W2 ----
    {
        const float DS = 0.015625f;   // 1/64, exact
        const int r0 = mw*16 + g, r1 = r0 + 8;
        const int i0 = idxI[r0], j0 = idxJ[r0], c0 = idxC[r0];
        const int i1 = idxI[r1], j1 = idxJ[r1], c1 = idxC[r1];
        float s0 = 0.f, s1 = 0.f;
        #pragma unroll
        for (int q = 0; q < 10; q++) {
            const int c = nw*80 + q*8 + 2*t4;
            float2 u0 = b2f(*(const unsigned*)(d_Ub + (size_t)i0*160 + c));
            float2 v0 = b2f(*(const unsigned*)(d_Vb + (size_t)j0*160 + c));
            float2 t0 = b2f(*(const unsigned*)(d_Tb + (size_t)c0*160 + c));
            float2 u1 = b2f(*(const unsigned*)(d_Ub + (size_t)i1*160 + c));
            float2 v1 = b2f(*(const unsigned*)(d_Vb + (size_t)j1*160 + c));
            float2 t1 = b2f(*(const unsigned*)(d_Tb + (size_t)c1*160 + c));
            float w0 = W2s[c], w1 = W2s[c + 1];
            float h00 = fmaxf(fmaf(acc[q][0], DS, u0.x + v0.x + t0.x), 0.f);
            float h01 = fmaxf(fmaf(acc[q][1], DS, u0.y + v0.y + t0.y), 0.f);
            float h10 = fmaxf(fmaf(acc[q][2], DS, u1.x + v1.x + t1.x), 0.f);
            float h11 = fmaxf(fmaf(acc[q][3], DS, u1.y + v1.y + t1.y), 0.f);
            s0 += h00*w0 + h01*w1;
            s1 += h10*w0 + h11*w1;
        }
        s0 += __shfl_xor_sync(0xffffffffu, s0, 1);
        s0 += __shfl_xor_sync(0xffffffffu, s0, 2);
        s1 += __shfl_xor_sync(0xffffffffu, s1, 1);
        s1 += __shfl_xor_sync(0xffffffffu, s1, 2);
        if (t4 == 0) {
            sred[r0*2 + nw] = s0;
            sred[r1*2 + nw] = s1;
        }
    }
    __syncthreads();
    if (t < 128) scores[t] = sred[t*2] + sred[t*2 + 1] + b2[0] + msum[t];
    __syncthreads();

    // ---- Softmax + pad ----
    if (wid < 2) {
        int sp = blockIdx.x*2 + wid;
        int cnt = d_cnt[sp];
        float x0 = scores[wid*64 + lane];
        float x1 = scores[wid*64 + 32 + lane];
        bool v0 = lane < cnt;
        bool v1 = (lane + 32) < cnt;
        float m = 0.f;                      // epsilon logit 0 is always in the max
        if (v0) m = fmaxf(m, x0);
        if (v1) m = fmaxf(m, x1);
        #pragma unroll
        for (int o = 16; o; o >>= 1) m = fmaxf(m, __shfl_xor_sync(0xffffffffu, m, o));
        float e0 = v0 ? expf(x0 - m) : 0.f;
        float e1 = v1 ? expf(x1 - m) : 0.f;
        float sum = e0 + e1;
        #pragma unroll
        for (int o = 16; o; o >>= 1) sum += __shfl_xor_sync(0xffffffffu, sum, o);
        float eps = expf(-m);
        float inv = 1.f / (sum + eps);
        float* op = out + (size_t)sp * 65;
        op[lane]      = v0 ? e0 * inv : 1000.0f;
        op[lane + 32] = v1 ? e1 * inv : 1000.0f;
        if (lane == 0) op[64] = eps * inv;
    }
}

// ---------------- launcher ----------------
extern "C" void kernel_launch(void* const* d_in, const int* in_sizes, int n_in,
                              void* d_out, int out_size) {
    const float* g   = (const float*)d_in[0];
    const float* msc = (const float*)d_in[1];
    const float* de  = (const float*)d_in[2];
    const float* ge  = (const float*)d_in[3];
    const float* se  = (const float*)d_in[4];
    const float* W1  = (const float*)d_in[5];
    const float* b1  = (const float*)d_in[6];
    const float* W2  = (const float*)d_in[7];
    const float* b2  = (const float*)d_in[8];
    const void* mi = d_in[9];
    const void* ai = d_in[10];
    const void* di = d_in[11];
    const void* gn = d_in[12];
    const void* sp = d_in[13];
    const void* ac = d_in[14];
    float* out = (float*)d_out;

    cudaFuncSetAttribute(k_main, cudaFuncAttributeMaxDynamicSharedMemorySize, SMEM_MAIN);

    k_detect<<<1, 32>>>((const unsigned*)mi);
    k_index<<<(PP + 255)/256, 256>>>(mi, ai, di, gn, sp, ac);
    k_gh<<<(NN*GG + 255)/256, 256>>>(g);
    k_wct<<<40, 256>>>(W1);
    k_T<<<(192*160 + 255)/256, 256>>>(de, ge, se, W1, b1);
    k_uv<<<NN/8, 160>>>(g, W1);
    k_main<<<SS/2, 512, SMEM_MAIN>>>(msc, W2, b2, out);
}

// round 17
// speedup vs baseline: 1.1282x; 1.1282x over previous
#include <cuda_runtime.h>
#include <cuda_bf16.h>
#include <cuda_fp16.h>
#include <cstdint>

#define SS 4096
#define KK 64
#define NN 4096
#define GG 512
#define PP (SS*KK)

// ---------------- scratch (no allocation allowed) ----------------
__device__ int d_flag64;
__device__ __align__(16) int d_mi[PP];
__device__ __align__(16) int d_ai[PP];
__device__ __align__(16) int d_phi[PP];
__device__ __align__(16) int d_cnt[SS];
__device__ __align__(16) __half d_gh[NN*GG];             // g_i in fp16
__device__ __align__(16) unsigned char d_wct[81920];     // W1c^T * 64, e4m3, k16n8k32-fragment order
__device__ __align__(16) uint2 d_wab[40960];             // [W1a | W1b]^T f16, m16n8k16-fragment order
__device__ __align__(16) __nv_bfloat16 d_Ub[NN*160];     // g @ W1a (bf16), pad cols zero
__device__ __align__(16) __nv_bfloat16 d_Vb[NN*160];     // g @ W1b (bf16)
__device__ __align__(16) __nv_bfloat16 d_Tb[192*160];    // phi-combo @ W1d + b1 (bf16)

// ---------------- helpers ----------------
__device__ __forceinline__ uint32_t smem_u32(const void* p) {
    uint32_t a;
    asm("{ .reg .u64 t; cvta.to.shared.u64 t, %1; cvt.u32.u64 %0, t; }" : "=r"(a) : "l"(p));
    return a;
}
__device__ __forceinline__ unsigned short f2e(float lo, float hi) {
    unsigned short r;
    asm("cvt.rn.satfinite.e4m3x2.f32 %0, %1, %2;" : "=h"(r) : "f"(hi), "f"(lo));
    return r;
}
__device__ __forceinline__ unsigned short h2e(unsigned h2) {
    unsigned short r;
    asm("cvt.rn.satfinite.e4m3x2.f16x2 %0, %1;" : "=h"(r) : "r"(h2));
    return r;
}
__device__ __forceinline__ unsigned hm2(unsigned x, unsigned y) {
    __half2 a = *reinterpret_cast<__half2*>(&x);
    __half2 b = *reinterpret_cast<__half2*>(&y);
    __half2 c = __hmul2(a, b);
    return *reinterpret_cast<unsigned*>(&c);
}
__device__ __forceinline__ float2 b2f(unsigned u) {
    __nv_bfloat162 h = *reinterpret_cast<__nv_bfloat162*>(&u);
    return __bfloat1622float2(h);
}

// ---------------- precompute kernels ----------------
__global__ void k_detect(const unsigned* __restrict__ m) {
    if (threadIdx.x == 0) {
        unsigned acc = 0;
        for (int t = 0; t < 64; t++) acc |= m[2*t + 1];
        d_flag64 = (acc == 0) ? 1 : 0;
    }
}

__global__ void k_index(const void* __restrict__ mi, const void* __restrict__ ai,
                        const void* __restrict__ di, const void* __restrict__ ge,
                        const void* __restrict__ sp, const void* __restrict__ ac) {
    int p = blockIdx.x * blockDim.x + threadIdx.x;
    int f = d_flag64;
    if (p < PP) {
        int a, b; long long d, gg, ss;
        if (f) {
            a = (int)((const long long*)mi)[p];
            b = (int)((const long long*)ai)[p];
            d  = ((const long long*)di)[p];
            gg = ((const long long*)ge)[p];
            ss = ((const long long*)sp)[p];
        } else {
            a = ((const int*)mi)[p];
            b = ((const int*)ai)[p];
            d  = ((const int*)di)[p];
            gg = ((const int*)ge)[p];
            ss = ((const int*)sp)[p];
        }
        int bk = (d>=1)+(d>=2)+(d>=3)+(d>=4)+(d>=8)+(d>=16)+(d>=32)+(d>=64);
        d_mi[p] = a;
        d_ai[p] = b;
        d_phi[p] = bk*21 + (int)gg*3 + (int)ss;
    }
    if (p < SS) {
        d_cnt[p] = f ? (int)((const long long*)ac)[p] : ((const int*)ac)[p];
    }
}

__global__ void k_gh(const float* __restrict__ g) {
    int i = blockIdx.x * 256 + threadIdx.x;
    if (i < NN*GG) d_gh[i] = __float2half(g[i]);
}

// W1c^T * 64 packed as e4m3 in m16n8k32 B-fragment order (validated in R14):
// uint2 index = (kc*20 + nf)*32 + lane
__global__ void k_wct(const float* __restrict__ W1) {
    int gid = blockIdx.x * 256 + threadIdx.x;
    if (gid < 10240) {
        int kc = gid / 640;
        int r  = gid - kc*640;
        int nf = r >> 5;
        int lane = r & 31;
        int n  = nf*8 + (lane >> 2);
        int t4 = lane & 3;
        float v[8];
        #pragma unroll
        for (int h = 0; h < 4; h++) {
            int k0 = kc*32 + 4*t4 + h;
            int k1 = k0 + 16;
            v[h]     = (n < 150) ? W1[(size_t)(1024 + k0)*150 + n] * 64.f : 0.f;
            v[4 + h] = (n < 150) ? W1[(size_t)(1024 + k1)*150 + n] * 64.f : 0.f;
        }
        uint2 w;
        w.x = (unsigned)f2e(v[0], v[1]) | ((unsigned)f2e(v[2], v[3]) << 16);
        w.y = (unsigned)f2e(v[4], v[5]) | ((unsigned)f2e(v[6], v[7]) << 16);
        ((uint2*)d_wct)[gid] = w;
    }
}

// [W1a | W1b] as f16 in m16n8k16 B-fragment order (layout validated in R13 bf16):
// uint2 index = (kc*40 + nf)*32 + lane ; n = nf*8 + lane/4 in [0,320)
//   n < 160 -> U column n (W1[k][n]) ; n >= 160 -> V column n-160 (W1[512+k][n-160])
__global__ void k_wab(const float* __restrict__ W1) {
    int gid = blockIdx.x * 256 + threadIdx.x;
    if (gid < 40960) {
        int kc = gid / 1280;
        int r  = gid - kc*1280;
        int nf = r >> 5;
        int lane = r & 31;
        int g = lane >> 2, t4 = lane & 3;
        int n = nf*8 + g;
        int col  = (n < 160) ? n : n - 160;
        int base = (n < 160) ? 0 : 512;
        bool ok = (col < 150);
        int k0 = kc*16 + 2*t4;
        float v0 = ok ? W1[(size_t)(base + k0)*150 + col] : 0.f;
        float v1 = ok ? W1[(size_t)(base + k0 + 1)*150 + col] : 0.f;
        float v2 = ok ? W1[(size_t)(base + k0 + 8)*150 + col] : 0.f;
        float v3 = ok ? W1[(size_t)(base + k0 + 9)*150 + col] : 0.f;
        __half2 h0 = __floats2half2_rn(v0, v1);
        __half2 h1 = __floats2half2_rn(v2, v3);
        uint2 w;
        w.x = *(unsigned*)&h0;
        w.y = *(unsigned*)&h1;
        d_wab[gid] = w;
    }
}

__global__ void k_T(const float* __restrict__ de, const float* __restrict__ ge,
                    const float* __restrict__ se, const float* __restrict__ W1,
                    const float* __restrict__ b1) {
    int gid = blockIdx.x * blockDim.x + threadIdx.x;
    if (gid >= 192*160) return;
    int c = gid / 160, m = gid % 160;
    int d = c / 21, rr = c % 21, gg = rr / 3, sp = rr % 3;
    float val = 0.f;
    if (m < 150 && d < 9) {
        val = b1[m];
        #pragma unroll 4
        for (int q = 0; q < 20; q++) {
            val += de[d*20 + q]  * W1[(size_t)(1536 + q)*150 + m];
            val += ge[gg*20 + q] * W1[(size_t)(1556 + q)*150 + m];
            val += se[sp*20 + q] * W1[(size_t)(1576 + q)*150 + m];
        }
    }
    d_Tb[gid] = __float2bfloat16(val);
}

// ---------------- U/V via tensor cores: [4096,512] @ [512,320] ----------------
// 32 CTAs x 128 rows. 512 threads / 16 warps: mw=wid>>1 (8 M-tiles of 16 rows),
// nw=wid&1 (0 -> U cols 0..159, 1 -> V cols 0..159). acc[20][4].
#define UV_STRIDE 1040
#define SMEM_UVM  (128*UV_STRIDE)

__global__ __launch_bounds__(512, 1) void k_uvm() {
    extern __shared__ char sm[];
    const int t = threadIdx.x;
    const int lane = t & 31, wid = t >> 5;
    const uint32_t sb = smem_u32(sm);
    const int pbase = blockIdx.x * 128;

    // coalesced copy of 128 g-rows (f16) into smem, odd 16B stride
    {
        const int pl = t & 127, qq = t >> 7;
        const uint4* src = (const uint4*)(d_gh + (size_t)(pbase + pl)*GG) + qq*16;
        char* rowp = sm + pl*UV_STRIDE + qq*256;
        #pragma unroll
        for (int e = 0; e < 16; e++) *(uint4*)(rowp + e*16) = src[e];
    }
    __syncthreads();

    const int mw = wid >> 1, nw = wid & 1;
    const int g = lane >> 2, t4 = lane & 3;
    const uint32_t arow = sb
        + (uint32_t)(mw*16 + (lane & 7) + (lane & 8)) * UV_STRIDE
        + (uint32_t)((lane >> 4) & 1) * 16;
    const uint2* wsrc = d_wab + (size_t)(nw*20)*32 + lane;

    float acc[20][4];
    #pragma unroll
    for (int q = 0; q < 20; q++)
        #pragma unroll
        for (int e = 0; e < 4; e++) acc[q][e] = 0.f;

    for (int kc = 0; kc < 32; kc++) {
        uint32_t a0, a1, a2, a3;
        asm volatile("ldmatrix.sync.aligned.m8n8.x4.shared.b16 {%0,%1,%2,%3}, [%4];"
                     : "=r"(a0), "=r"(a1), "=r"(a2), "=r"(a3)
                     : "r"(arow + (uint32_t)kc*32));
        #pragma unroll
        for (int q = 0; q < 20; q++) {
            uint2 bb = wsrc[(kc*40 + q)*32];
            asm volatile(
                "mma.sync.aligned.m16n8k16.row.col.f32.f16.f16.f32 "
                "{%0,%1,%2,%3}, {%4,%5,%6,%7}, {%8,%9}, {%0,%1,%2,%3};"
                : "+f"(acc[q][0]), "+f"(acc[q][1]), "+f"(acc[q][2]), "+f"(acc[q][3])
                : "r"(a0), "r"(a1), "r"(a2), "r"(a3), "r"(bb.x), "r"(bb.y));
        }
    }

    // store bf16 pairs to d_Ub (nw=0) / d_Vb (nw=1)
    {
        __nv_bfloat16* dst = nw ? d_Vb : d_Ub;
        const int r0 = pbase + mw*16 + g, r1 = r0 + 8;
        #pragma unroll
        for (int q = 0; q < 20; q++) {
            const int n = q*8 + 2*t4;                   // 0..158, even
            __nv_bfloat162 p0 = __floats2bfloat162_rn(acc[q][0], acc[q][1]);
            __nv_bfloat162 p1 = __floats2bfloat162_rn(acc[q][2], acc[q][3]);
            *(unsigned*)(dst + (size_t)r0*160 + n) = *(unsigned*)&p0;
            *(unsigned*)(dst + (size_t)r1*160 + n) = *(unsigned*)&p1;
        }
    }
}

// ---------------- main fused kernel (fp8 mma, 64-pair tiles, 2 CTAs/SM) ------
// CTA = 64 pairs = 1 span. 256 threads / 8 warps (4 M-tiles x 2 N-halves).
// Es [64 rows][stride 528B] e4m3 (row = 512 data bytes = 16 k32-chunks).
// W1c fp8 fragments streamed from global (L1-served across warps/CTAs).
#define ES_STRIDE 528
#define OFF_A    0
#define OFF_MSUM 33792
#define OFF_II   34048
#define OFF_JJ   34304
#define OFF_CC   34560
#define OFF_W2   34816
#define OFF_SC   35456
#define OFF_SR   35712
#define SMEM_MAIN 36352

__global__ __launch_bounds__(256, 2)
void k_main(const float* __restrict__ ms, const float* __restrict__ W2,
            const float* __restrict__ b2, float* __restrict__ out) {
    extern __shared__ char sm[];
    const int t = threadIdx.x;
    const int lane = t & 31, wid = t >> 5;
    const uint32_t sb = smem_u32(sm);
    const int pbase = blockIdx.x * 64;

    float* msum   = (float*)(sm + OFF_MSUM);
    int*   idxI   = (int*)(sm + OFF_II);
    int*   idxJ   = (int*)(sm + OFF_JJ);
    int*   idxC   = (int*)(sm + OFF_CC);
    float* W2s    = (float*)(sm + OFF_W2);
    float* scores = (float*)(sm + OFF_SC);
    float* sred   = (float*)(sm + OFF_SR);

    // ---- Phase A: gather + f16 product -> e4m3 Es tile ----
    {
        const int pl = t & 63, qq = t >> 6;   // 4 threads per pair, 128 elems each
        const int p = pbase + pl;
        const int i = d_mi[p], j = d_ai[p];
        if (qq == 0) {
            msum[pl] = ms[i] + ms[j];
            idxI[pl] = i; idxJ[pl] = j; idxC[pl] = d_phi[p];
        }
        const uint4* gi4 = (const uint4*)(d_gh + (size_t)i*GG) + qq*16;
        const uint4* gj4 = (const uint4*)(d_gh + (size_t)j*GG) + qq*16;
        char* rowp = sm + OFF_A + pl*ES_STRIDE + qq*128;
        #pragma unroll
        for (int e = 0; e < 8; e++) {
            uint4 a0 = gi4[2*e], a1 = gi4[2*e + 1];
            uint4 c0 = gj4[2*e], c1 = gj4[2*e + 1];
            unsigned p0 = hm2(a0.x, c0.x), p1 = hm2(a0.y, c0.y);
            unsigned p2 = hm2(a0.z, c0.z), p3 = hm2(a0.w, c0.w);
            unsigned p4 = hm2(a1.x, c1.x), p5 = hm2(a1.y, c1.y);
            unsigned p6 = hm2(a1.z, c1.z), p7 = hm2(a1.w, c1.w);
            uint4 r;
            r.x = (unsigned)h2e(p0) | ((unsigned)h2e(p1) << 16);
            r.y = (unsigned)h2e(p2) | ((unsigned)h2e(p3) << 16);
            r.z = (unsigned)h2e(p4) | ((unsigned)h2e(p5) << 16);
            r.w = (unsigned)h2e(p6) | ((unsigned)h2e(p7) << 16);
            *(uint4*)(rowp + e*16) = r;
        }
        if (t < 160) W2s[t] = (t < 150) ? __ldg(W2 + t) : 0.f;
    }
    __syncthreads();   // the ONLY barrier before the epilogue

    // ---- K loop: 16 chunks of k32, fp8 mma, B fragments from global (L1) ----
    const int mw = wid >> 1, nw = wid & 1;
    const int g = lane >> 2, t4 = lane & 3;

    const uint32_t arow = sb + OFF_A
        + (uint32_t)(mw*16 + (lane & 7) + (lane & 8)) * ES_STRIDE
        + (uint32_t)((lane >> 4) & 1) * 16;

    const uint2* wsrc = (const uint2*)d_wct + nw*320 + lane;

    float acc[10][4];
    #pragma unroll
    for (int q = 0; q < 10; q++)
        #pragma unroll
        for (int e = 0; e < 4; e++) acc[q][e] = 0.f;

    #pragma unroll 4
    for (int kc = 0; kc < 16; kc++) {
        uint32_t a0, a1, a2, a3;
        asm volatile("ldmatrix.sync.aligned.m8n8.x4.shared.b16 {%0,%1,%2,%3}, [%4];"
                     : "=r"(a0), "=r"(a1), "=r"(a2), "=r"(a3)
                     : "r"(arow + (uint32_t)kc*32));
        #pragma unroll
        for (int q = 0; q < 10; q++) {
            uint2 bb = wsrc[kc*640 + q*32];
            asm volatile(
                "mma.sync.aligned.m16n8k32.row.col.f32.e4m3.e4m3.f32 "
                "{%0,%1,%2,%3}, {%4,%5,%6,%7}, {%8,%9}, {%0,%1,%2,%3};"
                : "+f"(acc[q][0]), "+f"(acc[q][1]), "+f"(acc[q][2]), "+f"(acc[q][3])
                : "r"(a0), "r"(a1), "r"(a2), "r"(a3), "r"(bb.x), "r"(bb.y));
        }
    }

    // ---- Epilogue: acc/64 + U/V/T gather (bf16 from L2), ReLU, dot W2 ----
    {
        const float DS = 0.015625f;   // 1/64, exact
        const int r0 = mw*16 + g, r1 = r0 + 8;
        const int i0 = idxI[r0], j0 = idxJ[r0], c0 = idxC[r0];
        const int i1 = idxI[r1], j1 = idxJ[r1], c1 = idxC[r1];
        float s0 = 0.f, s1 = 0.f;
        #pragma unroll
        for (int q = 0; q < 10; q++) {
            const int c = nw*80 + q*8 + 2*t4;
            float2 u0 = b2f(*(const unsigned*)(d_Ub + (size_t)i0*160 + c));
            float2 v0 = b2f(*(const unsigned*)(d_Vb + (size_t)j0*160 + c));
            float2 t0 = b2f(*(const unsigned*)(d_Tb + (size_t)c0*160 + c));
            float2 u1 = b2f(*(const unsigned*)(d_Ub + (size_t)i1*160 + c));
            float2 v1 = b2f(*(const unsigned*)(d_Vb + (size_t)j1*160 + c));
            float2 t1 = b2f(*(const unsigned*)(d_Tb + (size_t)c1*160 + c));
            float w0 = W2s[c], w1 = W2s[c + 1];
            float h00 = fmaxf(fmaf(acc[q][0], DS, u0.x + v0.x + t0.x), 0.f);
            float h01 = fmaxf(fmaf(acc[q][1], DS, u0.y + v0.y + t0.y), 0.f);
            float h10 = fmaxf(fmaf(acc[q][2], DS, u1.x + v1.x + t1.x), 0.f);
            float h11 = fmaxf(fmaf(acc[q][3], DS, u1.y + v1.y + t1.y), 0.f);
            s0 += h00*w0 + h01*w1;
            s1 += h10*w0 + h11*w1;
        }
        s0 += __shfl_xor_sync(0xffffffffu, s0, 1);
        s0 += __shfl_xor_sync(0xffffffffu, s0, 2);
        s1 += __shfl_xor_sync(0xffffffffu, s1, 1);
        s1 += __shfl_xor_sync(0xffffffffu, s1, 2);
        if (t4 == 0) {
            sred[r0*2 + nw] = s0;
            sred[r1*2 + nw] = s1;
        }
    }
    __syncthreads();
    if (t < 64) scores[t] = sred[t*2] + sred[t*2 + 1] + b2[0] + msum[t];
    __syncthreads();

    // ---- Softmax + pad (1 span per CTA) ----
    if (wid == 0) {
        int sp = blockIdx.x;
        int cnt = d_cnt[sp];
        float x0 = scores[lane];
        float x1 = scores[lane + 32];
        bool v0 = lane < cnt;
        bool v1 = (lane + 32) < cnt;
        float m = 0.f;                      // epsilon logit 0 is always in the max
        if (v0) m = fmaxf(m, x0);
        if (v1) m = fmaxf(m, x1);
        #pragma unroll
        for (int o = 16; o; o >>= 1) m = fmaxf(m, __shfl_xor_sync(0xffffffffu, m, o));
        float e0 = v0 ? expf(x0 - m) : 0.f;
        float e1 = v1 ? expf(x1 - m) : 0.f;
        float sum = e0 + e1;
        #pragma unroll
        for (int o = 16; o; o >>= 1) sum += __shfl_xor_sync(0xffffffffu, sum, o);
        float eps = expf(-m);
        float inv = 1.f / (sum + eps);
        float* op = out + (size_t)sp * 65;
        op[lane]      = v0 ? e0 * inv : 1000.0f;
        op[lane + 32] = v1 ? e1 * inv : 1000.0f;
        if (lane == 0) op[64] = eps * inv;
    }
}

// ---------------- launcher ----------------
extern "C" void kernel_launch(void* const* d_in, const int* in_sizes, int n_in,
                              void* d_out, int out_size) {
    const float* g   = (const float*)d_in[0];
    const float* msc = (const float*)d_in[1];
    const float* de  = (const float*)d_in[2];
    const float* ge  = (const float*)d_in[3];
    const float* se  = (const float*)d_in[4];
    const float* W1  = (const float*)d_in[5];
    const float* b1  = (const float*)d_in[6];
    const float* W2  = (const float*)d_in[7];
    const float* b2  = (const float*)d_in[8];
    const void* mi = d_in[9];
    const void* ai = d_in[10];
    const void* di = d_in[11];
    const void* gn = d_in[12];
    const void* sp = d_in[13];
    const void* ac = d_in[14];
    float* out = (float*)d_out;

    cudaFuncSetAttribute(k_uvm, cudaFuncAttributeMaxDynamicSharedMemorySize, SMEM_UVM);
    cudaFuncSetAttribute(k_main, cudaFuncAttributeMaxDynamicSharedMemorySize, SMEM_MAIN);

    k_detect<<<1, 32>>>((const unsigned*)mi);
    k_index<<<(PP + 255)/256, 256>>>(mi, ai, di, gn, sp, ac);
    k_gh<<<(NN*GG + 255)/256, 256>>>(g);
    k_wct<<<40, 256>>>(W1);
    k_wab<<<160, 256>>>(W1);
    k_T<<<(192*160 + 255)/256, 256>>>(de, ge, se, W1, b1);
    k_uvm<<<NN/128, 512, SMEM_UVM>>>();
    k_main<<<SS, 256, SMEM_MAIN>>>(msc, W2, b2, out);
}